// round 8
// baseline (speedup 1.0000x reference)
#include <cuda_runtime.h>
#include <math.h>

#define HW   65536
#define IMG  6291456          // 96*65536
#define NPIX 25165824         // 4*96*65536
#define SCALE 0.17677669529663687f

typedef unsigned long long ull;

// Full-batch buffers. g_Q / g_K are reused as D0 / D1 scratch after attention.
static __device__ __align__(16) float g_V[NPIX];
static __device__ __align__(16) float g_aV[NPIX];
static __device__ __align__(16) float g_Q[NPIX];
static __device__ __align__(16) float g_K[NPIX];
static __device__ __align__(16) float g_attn[NPIX];
static __device__ __align__(16) float g_bias[3 * 64 * 64];

// ---- f32x2 packed helpers --------------------------------------------------
__device__ __forceinline__ ull pk(float x) {
    ull r; asm("mov.b64 %0, {%1, %1};" : "=l"(r) : "f"(x)); return r;
}
__device__ __forceinline__ float2 upk(ull v) {
    float2 f; asm("mov.b64 {%0, %1}, %2;" : "=f"(f.x), "=f"(f.y) : "l"(v)); return f;
}
__device__ __forceinline__ ull fma2(ull a, ull b, ull c) {
    ull r; asm("fma.rn.f32x2 %0, %1, %2, %3;" : "=l"(r) : "l"(a), "l"(b), "l"(c)); return r;
}
__device__ __forceinline__ ull mul2(ull a, ull b) {
    ull r; asm("mul.rn.f32x2 %0, %1, %2;" : "=l"(r) : "l"(a), "l"(b)); return r;
}

// ---------------------------------------------------------------------------
// K1: relative-position bias MLP
// ---------------------------------------------------------------------------
__device__ __forceinline__ float sgnlog(int d) {
    float l = log1pf(fabsf((float)d));
    return d < 0 ? -l : l;
}

__global__ void bias_kernel(const float* __restrict__ mw1, const float* __restrict__ mb1,
                            const float* __restrict__ mw2, const float* __restrict__ mb2) {
    int t = blockIdx.x * 256 + threadIdx.x;
    if (t >= 4096) return;
    int i = t >> 6, j = t & 63;
    float r0 = sgnlog((i >> 3) - (j >> 3));
    float r1 = sgnlog((i & 7) - (j & 7));
    float a0 = 0.f, a1 = 0.f, a2 = 0.f;
    for (int h = 0; h < 256; h++) {
        float hid = fmaf(r0, mw1[h], fmaf(r1, mw1[256 + h], mb1[h]));
        hid = fmaxf(hid, 0.f);
        a0 = fmaf(hid, mw2[h * 3 + 0], a0);
        a1 = fmaf(hid, mw2[h * 3 + 1], a1);
        a2 = fmaf(hid, mw2[h * 3 + 2], a2);
    }
    g_bias[t]        = a0 + mb2[0];
    g_bias[4096 + t] = a1 + mb2[1];
    g_bias[8192 + t] = a2 + mb2[2];
}

// ---------------------------------------------------------------------------
// K2: conv1x1 96->96, FFMA-bound tiling.
// 128 threads/block, tile = 96 out x 128 px. Per thread: u=6 outs x v=8 pairs.
// Per warp c-iter: 6 broadcast LDS.32 + 8 LDS.64 = 22 wf for 48 FFMA2.
// smem: s_in2[96][66] ull (50688) + s_w[96][97] f (37248) + s_b[96] = 88320 B
// ---------------------------------------------------------------------------
struct ConvJob { const float* in; const float* w; const float* bias; float* out; float scale; };

__global__ __launch_bounds__(128, 2)
void conv_kernel(ConvJob j0, ConvJob j1, ConvJob j2, ConvJob j3) {
    ConvJob j = (blockIdx.z == 0) ? j0 : (blockIdx.z == 1) ? j1 : (blockIdx.z == 2) ? j2 : j3;
    extern __shared__ char raw[];
    ull*   s_in2 = (ull*)raw;                 // 96*66 ull
    float* s_w   = (float*)(raw + 6336 * 8);  // 96*97 f
    float* s_b   = s_w + 9312;                // 96
    int tid = threadIdx.x;
    int bx = blockIdx.x;
    int b = bx >> 9, px0 = (bx & 511) << 7;
    const float* inb = j.in + b * IMG + px0;
    float* outb = j.out + b * IMG + px0;

    for (int l = tid; l < 9216; l += 128) s_w[(l / 96) * 97 + (l % 96)] = j.w[l];
    if (tid < 96) s_b[tid] = j.bias[tid];
    for (int l = tid; l < 6144; l += 128) {
        int c = l >> 6, p2 = l & 63;
        s_in2[c * 66 + p2] = *(const ull*)(inb + c * HW + 2 * p2);
    }
    __syncthreads();

    int og = tid >> 3, pg = tid & 7;   // o = og+16u (u<6); pair = pg+8v (v<8)
    ull acc[6][8];
    #pragma unroll
    for (int u = 0; u < 6; u++)
        #pragma unroll
        for (int v = 0; v < 8; v++) acc[u][v] = 0ull;

    #pragma unroll 2
    for (int c = 0; c < 96; c++) {
        ull w2[6], pf[8];
        #pragma unroll
        for (int u = 0; u < 6; u++) w2[u] = pk(s_w[(og + 16 * u) * 97 + c]);
        #pragma unroll
        for (int v = 0; v < 8; v++) pf[v] = s_in2[c * 66 + pg + 8 * v];
        #pragma unroll
        for (int u = 0; u < 6; u++)
            #pragma unroll
            for (int v = 0; v < 8; v++) acc[u][v] = fma2(w2[u], pf[v], acc[u][v]);
    }

    ull s2 = pk(j.scale);
    #pragma unroll
    for (int u = 0; u < 6; u++) {
        int o = og + 16 * u;
        ull b2 = pk(s_b[o] * j.scale);
        ull* op = (ull*)(outb + o * HW);
        #pragma unroll
        for (int v = 0; v < 8; v++)
            op[pg + 8 * v] = fma2(acc[u][v], s2, b2);
    }
}

// ---------------------------------------------------------------------------
// K3: window attention — one thread per (head, row); one barrier.
// smem floats: s_q[3][64*33] | s_k ull[3][32*33] | s_v[3][64*34] = 76800 B
// ---------------------------------------------------------------------------
__global__ __launch_bounds__(192, 2)
void attn_kernel() {
    extern __shared__ float sm[];
    float* s_q = sm;                      // [h][n*33+d]
    ull*   s_k = (ull*)(sm + 6336);       // [h][d*33+m2]
    float* s_v = sm + 12672;              // [h][m*34+d]

    int tid = threadIdx.x;
    int blk = blockIdx.x;
    int b = blk >> 10, wy = (blk >> 5) & 31, wx = blk & 31;
    int pixoff = b * IMG + wy * 2048 + wx * 8;

    for (int l = tid; l < 3072; l += 192) {
        int hh = l >> 10;
        int r = l & 1023;
        int d = r >> 5, n2 = r & 31;
        int ga = pixoff + (hh * 32 + d) * HW + (n2 >> 2) * 256 + (n2 & 3) * 2;
        float2 q = upk(*(const ull*)(g_Q + ga));
        s_q[hh * 2112 + (2 * n2) * 33 + d] = q.x;
        s_q[hh * 2112 + (2 * n2 + 1) * 33 + d] = q.y;
        s_k[hh * 1056 + d * 33 + n2] = *(const ull*)(g_K + ga);
        float2 v = upk(*(const ull*)(g_V + ga));
        s_v[hh * 2176 + (2 * n2) * 34 + d] = v.x;
        s_v[hh * 2176 + (2 * n2 + 1) * 34 + d] = v.y;
    }
    __syncthreads();

    int h = tid >> 6, n = tid & 63;
    const float* qrow = s_q + h * 2112 + n * 33;
    const ull*   kh   = s_k + h * 1056;
    const float* vh   = s_v + h * 2176;

    ull acc[32];
    {
        const ull* bias2 = (const ull*)(g_bias + h * 4096 + n * 64);
        #pragma unroll
        for (int m2 = 0; m2 < 32; m2++) acc[m2] = bias2[m2];
    }
    #pragma unroll 4
    for (int d = 0; d < 32; d++) {
        ull qd = pk(qrow[d]);
        const ull* krow = kh + d * 33;
        #pragma unroll
        for (int m2 = 0; m2 < 32; m2++) acc[m2] = fma2(qd, krow[m2], acc[m2]);
    }

    float p[64];
    #pragma unroll
    for (int m2 = 0; m2 < 32; m2++) {
        float2 f = upk(acc[m2]);
        p[2 * m2] = f.x; p[2 * m2 + 1] = f.y;
    }
    float mx = p[0];
    #pragma unroll
    for (int k = 1; k < 64; k++) mx = fmaxf(mx, p[k]);
    float sum = 0.f;
    #pragma unroll
    for (int k = 0; k < 64; k++) { p[k] = __expf(p[k] - mx); sum += p[k]; }
    float rinv = 1.f / sum;

    ull oacc[16];
    #pragma unroll
    for (int d2 = 0; d2 < 16; d2++) oacc[d2] = 0ull;
    #pragma unroll
    for (int m = 0; m < 64; m++) {
        ull pm = pk(p[m]);
        const float* vrow = vh + m * 34;
        #pragma unroll
        for (int d2 = 0; d2 < 16; d2++)
            oacc[d2] = fma2(pm, *(const ull*)(vrow + 2 * d2), oacc[d2]);
    }
    ull rr = pk(rinv);
    float* ob = g_attn + pixoff + (n >> 3) * 256 + (n & 7);
    #pragma unroll
    for (int d2 = 0; d2 < 16; d2++) {
        float2 f = upk(mul2(oacc[d2], rr));
        ob[(h * 32 + 2 * d2) * HW] = f.x;
        ob[(h * 32 + 2 * d2 + 1) * HW] = f.y;
    }
}

// ---------------------------------------------------------------------------
// K4: fused-z depthwise 5x5 + bias + attn -> D0 (g_Q), D1 (g_K). grid 6144.
// ---------------------------------------------------------------------------
__global__ __launch_bounds__(256)
void dw_kernel(const float* __restrict__ wdw, const float* __restrict__ bdw,
               const float* __restrict__ wdwa, const float* __restrict__ bdwa) {
    extern __shared__ float st[];
    float* s_h0 = st;                  // [20][264]
    float* s_h1 = st + 5280;
    float* s_w0 = st + 10560;
    float* s_w1 = st + 10592;

    int bx = blockIdx.x;               // 6144 = 16 * 96 * 4
    int yt = bx & 15;
    int v = bx >> 4;
    int c = v % 96, b = v / 96;
    int y0 = yt << 4;
    int tid = threadIdx.x;
    int chan = b * IMG + c * HW;
    const float* Vc  = g_V  + chan;
    const float* aVc = g_aV + chan;

    for (int l = tid; l < 5200; l += 256) {
        int r = l / 260, q = l - r * 260;
        int yy = y0 + r - 2; yy = yy < 0 ? -yy : (yy > 255 ? 510 - yy : yy);
        int xx = q - 2;      xx = xx < 0 ? -xx : (xx > 255 ? 510 - xx : xx);
        int ga = yy * 256 + xx;
        s_h0[r * 264 + q] = Vc[ga];
        s_h1[r * 264 + q] = aVc[ga];
    }
    if (tid < 25) { s_w0[tid] = wdw[c * 25 + tid]; s_w1[tid] = wdwa[c * 25 + tid]; }
    __syncthreads();

    int col = tid;
    float av[16];
    const float* ab = g_attn + chan + y0 * 256 + col;
    #pragma unroll
    for (int r = 0; r < 16; r++) av[r] = ab[r * 256];

    #pragma unroll
    for (int z = 0; z < 2; z++) {
        const float* sh = z ? s_h1 : s_h0;
        const float* sw = z ? s_w1 : s_w0;
        float bias = z ? __ldg(&bdwa[c]) : __ldg(&bdw[c]);
        float w[25];
        #pragma unroll
        for (int k = 0; k < 25; k++) w[k] = sw[k];

        float acc[16];
        #pragma unroll
        for (int r = 0; r < 16; r++) acc[r] = bias + av[r];

        #pragma unroll
        for (int rr = 0; rr < 20; rr++) {
            float xv[5];
            #pragma unroll
            for (int dx = 0; dx < 5; dx++) xv[dx] = sh[rr * 264 + col + dx];
            #pragma unroll
            for (int dy = 0; dy < 5; dy++) {
                int r = rr - dy;
                if (r >= 0 && r < 16) {
                    #pragma unroll
                    for (int dx = 0; dx < 5; dx++)
                        acc[r] = fmaf(xv[dx], w[dy * 5 + dx], acc[r]);
                }
            }
        }

        float* db = (z ? g_K : g_Q) + chan + y0 * 256 + col;
        #pragma unroll
        for (int r = 0; r < 16; r++)
            db[r * 256] = acc[r];
    }
}

// ---------------------------------------------------------------------------
extern "C" void kernel_launch(void* const* d_in, const int* in_sizes, int n_in,
                              void* d_out, int out_size) {
    const float* vision     = (const float*)d_in[0];
    const float* ass_vision = (const float*)d_in[1];
    const float* wv   = (const float*)d_in[2];
    const float* bv   = (const float*)d_in[3];
    const float* wav  = (const float*)d_in[4];
    const float* bav  = (const float*)d_in[5];
    const float* wqk  = (const float*)d_in[6];
    const float* bqk  = (const float*)d_in[7];
    // d_in[8..9]: waqk/baqk dead (reference bug: aaw unused, ass_attn_out = attn_out)
    const float* wdw  = (const float*)d_in[10];
    const float* bdw  = (const float*)d_in[11];
    const float* wdwa = (const float*)d_in[12];
    const float* bdwa = (const float*)d_in[13];
    const float* wp   = (const float*)d_in[14];
    const float* bp   = (const float*)d_in[15];
    const float* wpa  = (const float*)d_in[16];
    const float* bpa  = (const float*)d_in[17];
    const float* mw1  = (const float*)d_in[18];
    const float* mb1  = (const float*)d_in[19];
    const float* mw2  = (const float*)d_in[20];
    const float* mb2  = (const float*)d_in[21];
    float* out = (float*)d_out;

    float *pV, *paV, *pQ, *pK;
    cudaGetSymbolAddress((void**)&pV,  g_V);
    cudaGetSymbolAddress((void**)&paV, g_aV);
    cudaGetSymbolAddress((void**)&pQ,  g_Q);
    cudaGetSymbolAddress((void**)&pK,  g_K);

    const int SMEM_CONV = 6336 * 8 + 9312 * 4 + 96 * 4;   // 88320
    const int SMEM_ATTN = 19200 * 4;                       // 76800
    const int SMEM_DW   = 10624 * 4;                       // 42496
    cudaFuncSetAttribute(conv_kernel, cudaFuncAttributeMaxDynamicSharedMemorySize, SMEM_CONV);
    cudaFuncSetAttribute(attn_kernel, cudaFuncAttributeMaxDynamicSharedMemorySize, SMEM_ATTN);
    cudaFuncSetAttribute(dw_kernel,   cudaFuncAttributeMaxDynamicSharedMemorySize, SMEM_DW);

    bias_kernel<<<16, 256>>>(mw1, mb1, mw2, mb2);

    // V, Q (pre-scaled), K, aV: 4 independent jobs
    ConvJob jV  = { vision,     wv,         bv,       pV,  1.0f };
    ConvJob jQ  = { vision,     wqk,        bqk,      pQ,  SCALE };
    ConvJob jK  = { vision,     wqk + 9216, bqk + 96, pK,  1.0f };
    ConvJob jaV = { ass_vision, wav,        bav,      paV, 1.0f };
    conv_kernel<<<dim3(2048, 1, 4), 128, SMEM_CONV>>>(jV, jQ, jK, jaV);

    // window attention: 4096 windows, 192 threads (3 heads x 64 rows)
    attn_kernel<<<4096, 192, SMEM_ATTN>>>();

    // depthwise + attn add -> D0 (g_Q), D1 (g_K)
    dw_kernel<<<6144, 256, SMEM_DW>>>(wdw, bdw, wdwa, bdwa);

    // final projections
    ConvJob jP0 = { pQ, wp,  bp,  out,        1.0f };
    ConvJob jP1 = { pK, wpa, bpa, out + NPIX, 1.0f };
    conv_kernel<<<dim3(2048, 1, 2), 128, SMEM_CONV>>>(jP0, jP1, jP0, jP0);
}

// round 9
// speedup vs baseline: 1.1853x; 1.1853x over previous
#include <cuda_runtime.h>
#include <math.h>

#define HW   65536
#define IMG  6291456          // 96*65536
#define NPIX 25165824         // 4*96*65536
#define SCALE 0.17677669529663687f

typedef unsigned long long ull;

// Full-batch buffers. g_Q / g_K are reused as D0 / D1 scratch after attention.
static __device__ __align__(16) float g_V[NPIX];
static __device__ __align__(16) float g_aV[NPIX];
static __device__ __align__(16) float g_Q[NPIX];
static __device__ __align__(16) float g_K[NPIX];
static __device__ __align__(16) float g_attn[NPIX];
static __device__ __align__(16) float g_bias[3 * 64 * 64];

// ---- f32x2 packed helpers (attention) --------------------------------------
__device__ __forceinline__ ull pk(float x) {
    ull r; asm("mov.b64 %0, {%1, %1};" : "=l"(r) : "f"(x)); return r;
}
__device__ __forceinline__ float2 upk(ull v) {
    float2 f; asm("mov.b64 {%0, %1}, %2;" : "=f"(f.x), "=f"(f.y) : "l"(v)); return f;
}
__device__ __forceinline__ ull fma2(ull a, ull b, ull c) {
    ull r; asm("fma.rn.f32x2 %0, %1, %2, %3;" : "=l"(r) : "l"(a), "l"(b), "l"(c)); return r;
}
__device__ __forceinline__ ull mul2(ull a, ull b) {
    ull r; asm("mul.rn.f32x2 %0, %1, %2;" : "=l"(r) : "l"(a), "l"(b)); return r;
}

// ---- mma.sync helpers -------------------------------------------------------
__device__ __forceinline__ unsigned smem_u32(const void* p) {
    unsigned a;
    asm("{ .reg .u64 t; cvta.to.shared.u64 t, %1; cvt.u32.u64 %0, t; }" : "=r"(a) : "l"(p));
    return a;
}
__device__ __forceinline__ void ldsm4(unsigned* r, unsigned addr) {
    asm volatile("ldmatrix.sync.aligned.m8n8.x4.shared.b16 {%0,%1,%2,%3}, [%4];"
                 : "=r"(r[0]), "=r"(r[1]), "=r"(r[2]), "=r"(r[3]) : "r"(addr));
}
__device__ __forceinline__ void mma_bf16(float* c, const unsigned* a, unsigned b0, unsigned b1) {
    asm volatile(
        "mma.sync.aligned.m16n8k16.row.col.f32.bf16.bf16.f32 "
        "{%0,%1,%2,%3}, {%4,%5,%6,%7}, {%8,%9}, {%0,%1,%2,%3};"
        : "+f"(c[0]), "+f"(c[1]), "+f"(c[2]), "+f"(c[3])
        : "r"(a[0]), "r"(a[1]), "r"(a[2]), "r"(a[3]), "r"(b0), "r"(b1));
}
// pack 2 floats -> bf16x2 {lo=v0, hi=v1}
__device__ __forceinline__ unsigned cvt2(float v0, float v1) {
    unsigned r; asm("cvt.rn.bf16x2.f32 %0, %1, %2;" : "=r"(r) : "f"(v1), "f"(v0)); return r;
}

// swizzled smem byte offsets: row stride 384 B, 16B-window XOR by (row&7)
__device__ __forceinline__ int physA(int px, int kb) { return px * 384 + (kb ^ ((px & 7) << 4)); }
__device__ __forceinline__ int physB(int o,  int kb) { return o  * 384 + (kb ^ ((o  & 7) << 4)); }

#define SM_A 0
#define SM_B 49152
#define SM_BIAS 86016
#define SM_TOTAL 86400

// ---------------------------------------------------------------------------
// K1: relative-position bias MLP
// ---------------------------------------------------------------------------
__device__ __forceinline__ float sgnlog(int d) {
    float l = log1pf(fabsf((float)d));
    return d < 0 ? -l : l;
}

__global__ void bias_kernel(const float* __restrict__ mw1, const float* __restrict__ mb1,
                            const float* __restrict__ mw2, const float* __restrict__ mb2) {
    int t = blockIdx.x * 256 + threadIdx.x;
    if (t >= 4096) return;
    int i = t >> 6, j = t & 63;
    float r0 = sgnlog((i >> 3) - (j >> 3));
    float r1 = sgnlog((i & 7) - (j & 7));
    float a0 = 0.f, a1 = 0.f, a2 = 0.f;
    for (int h = 0; h < 256; h++) {
        float hid = fmaf(r0, mw1[h], fmaf(r1, mw1[256 + h], mb1[h]));
        hid = fmaxf(hid, 0.f);
        a0 = fmaf(hid, mw2[h * 3 + 0], a0);
        a1 = fmaf(hid, mw2[h * 3 + 1], a1);
        a2 = fmaf(hid, mw2[h * 3 + 2], a2);
    }
    g_bias[t]        = a0 + mb2[0];
    g_bias[4096 + t] = a1 + mb2[1];
    g_bias[8192 + t] = a2 + mb2[2];
}

// ---------------------------------------------------------------------------
// K2: conv1x1 96->96 via mma.sync bf16 split-2.
// D[px][o] = sum_c In[c][px] * W[o][c]  ~=  AhBh + AhBl + AlBh.
// A: s_A[px][k] k=0..191 (hi 0..95, lo 96..191), swizzled, stride 384 B.
// B: s_B[o][k] same layout. Block 256 thr = 8 warps (4 m x 2 n).
// ---------------------------------------------------------------------------
struct ConvJob { const float* in; const float* w; const float* bias; float* out; float scale; };

__global__ __launch_bounds__(256, 2)
void conv_kernel(ConvJob j0, ConvJob j1, ConvJob j2, ConvJob j3) {
    ConvJob j = (blockIdx.z == 0) ? j0 : (blockIdx.z == 1) ? j1 : (blockIdx.z == 2) ? j2 : j3;
    extern __shared__ __align__(16) char raw[];
    float* s_bias = (float*)(raw + SM_BIAS);

    int tid = threadIdx.x;
    int wid = tid >> 5, lane = tid & 31;
    int bx = blockIdx.x;
    int b = bx >> 9, px0 = (bx & 511) << 7;
    const float* inb = j.in + b * IMG + px0;

    if (tid < 96) s_bias[tid] = j.bias[tid];

    // ---- A conversion: In[c][px] -> s_A[px][c](hi), s_A[px][96+c](lo) ----
    {
        int c2 = lane >> 3, pxl = lane & 7;   // 4 c-pairs x 8 px per warp-iter
        #pragma unroll 4
        for (int it = 0; it < 24; it++) {
            int g = it * 8 + wid;             // 0..191
            int po = g & 15, cq = g >> 4;     // 16 px-octets x 12 c-quads
            int c = cq * 8 + c2 * 2;
            int px = po * 8 + pxl;
            float v0 = inb[c * HW + px];
            float v1 = inb[(c + 1) * HW + px];
            unsigned hi = cvt2(v0, v1);
            float h0 = __uint_as_float(hi << 16);
            float h1 = __uint_as_float(hi & 0xffff0000u);
            unsigned lo = cvt2(v0 - h0, v1 - h1);
            *(unsigned*)(raw + SM_A + physA(px, c * 2))         = hi;
            *(unsigned*)(raw + SM_A + physA(px, 192 + c * 2))   = lo;
        }
    }

    // ---- B conversion: W[o][c] -> s_B[o][c](hi), s_B[o][96+c](lo) ----
    for (int l = tid; l < 4608; l += 256) {
        int o = l / 48, cp = l - (l / 48) * 48;
        int c = cp * 2;
        float2 wv = upk(*(const ull*)(j.w + o * 96 + c));
        unsigned hi = cvt2(wv.x, wv.y);
        float h0 = __uint_as_float(hi << 16);
        float h1 = __uint_as_float(hi & 0xffff0000u);
        unsigned lo = cvt2(wv.x - h0, wv.y - h1);
        *(unsigned*)(raw + SM_B + physB(o, c * 2))       = hi;
        *(unsigned*)(raw + SM_B + physB(o, 192 + c * 2)) = lo;
    }
    __syncthreads();

    // ---- MMA mainloop ----
    unsigned sA32 = smem_u32(raw + SM_A);
    unsigned sB32 = smem_u32(raw + SM_B);
    int wm = wid >> 1, wn = wid & 1;
    int gr = lane & 7, gi = lane >> 3;
    int swz = gr << 4;
    int kextA = (gi >> 1) << 4;   // bytes
    int kextB = (gi & 1) << 4;
    int aRow[2], bRow[3];
    #pragma unroll
    for (int tm = 0; tm < 2; tm++)
        aRow[tm] = (wm * 32 + tm * 16 + gr + (gi & 1) * 8) * 384;
    #pragma unroll
    for (int tp = 0; tp < 3; tp++)
        bRow[tp] = (wn * 48 + tp * 16 + gr + (gi >> 1) * 8) * 384;

    float c[2][6][4];
    #pragma unroll
    for (int tm = 0; tm < 2; tm++)
        #pragma unroll
        for (int tn = 0; tn < 6; tn++)
            #pragma unroll
            for (int q = 0; q < 4; q++) c[tm][tn][q] = 0.f;

    #pragma unroll
    for (int t = 0; t < 3; t++) {
        int kaB = (t == 2) ? 192 : 0;     // A lo for term 2
        int kbB = (t == 1) ? 192 : 0;     // B lo for term 1
        #pragma unroll
        for (int ks = 0; ks < 6; ks++) {
            unsigned aF[2][4], bF[3][4];
            int ka = kaB + ks * 32;
            int kb = kbB + ks * 32;
            #pragma unroll
            for (int tm = 0; tm < 2; tm++)
                ldsm4(aF[tm], sA32 + aRow[tm] + ((ka + kextA) ^ swz));
            #pragma unroll
            for (int tp = 0; tp < 3; tp++)
                ldsm4(bF[tp], sB32 + bRow[tp] + ((kb + kextB) ^ swz));
            #pragma unroll
            for (int tm = 0; tm < 2; tm++)
                #pragma unroll
                for (int tn = 0; tn < 6; tn++) {
                    int tp = tn >> 1, r0 = (tn & 1) * 2;
                    mma_bf16(c[tm][tn], aF[tm], bF[tp][r0], bF[tp][r0 + 1]);
                }
        }
    }

    // ---- epilogue: direct STG, bias + scale fused ----
    {
        float* outb = j.out + b * IMG + px0;
        float scl = j.scale;
        int pr = lane >> 2, oc = (lane & 3) * 2;
        #pragma unroll
        for (int tm = 0; tm < 2; tm++) {
            int pxr = wm * 32 + tm * 16 + pr;
            #pragma unroll
            for (int tn = 0; tn < 6; tn++) {
                int o0 = wn * 48 + tn * 8 + oc;
                float b0 = s_bias[o0], b1 = s_bias[o0 + 1];
                outb[o0 * HW + pxr]            = (c[tm][tn][0] + b0) * scl;
                outb[(o0 + 1) * HW + pxr]      = (c[tm][tn][1] + b1) * scl;
                outb[o0 * HW + pxr + 8]        = (c[tm][tn][2] + b0) * scl;
                outb[(o0 + 1) * HW + pxr + 8]  = (c[tm][tn][3] + b1) * scl;
            }
        }
    }
}

// ---------------------------------------------------------------------------
// K3: window attention — one thread per (head, row); one barrier.
// smem floats: s_q[3][64*33] | s_k ull[3][32*33] | s_v[3][64*34] = 76800 B
// ---------------------------------------------------------------------------
__global__ __launch_bounds__(192, 2)
void attn_kernel() {
    extern __shared__ float sm[];
    float* s_q = sm;                      // [h][n*33+d]
    ull*   s_k = (ull*)(sm + 6336);       // [h][d*33+m2]
    float* s_v = sm + 12672;              // [h][m*34+d]

    int tid = threadIdx.x;
    int blk = blockIdx.x;
    int b = blk >> 10, wy = (blk >> 5) & 31, wx = blk & 31;
    int pixoff = b * IMG + wy * 2048 + wx * 8;

    for (int l = tid; l < 3072; l += 192) {
        int hh = l >> 10;
        int r = l & 1023;
        int d = r >> 5, n2 = r & 31;
        int ga = pixoff + (hh * 32 + d) * HW + (n2 >> 2) * 256 + (n2 & 3) * 2;
        float2 q = upk(*(const ull*)(g_Q + ga));
        s_q[hh * 2112 + (2 * n2) * 33 + d] = q.x;
        s_q[hh * 2112 + (2 * n2 + 1) * 33 + d] = q.y;
        s_k[hh * 1056 + d * 33 + n2] = *(const ull*)(g_K + ga);
        float2 v = upk(*(const ull*)(g_V + ga));
        s_v[hh * 2176 + (2 * n2) * 34 + d] = v.x;
        s_v[hh * 2176 + (2 * n2 + 1) * 34 + d] = v.y;
    }
    __syncthreads();

    int h = tid >> 6, n = tid & 63;
    const float* qrow = s_q + h * 2112 + n * 33;
    const ull*   kh   = s_k + h * 1056;
    const float* vh   = s_v + h * 2176;

    ull acc[32];
    {
        const ull* bias2 = (const ull*)(g_bias + h * 4096 + n * 64);
        #pragma unroll
        for (int m2 = 0; m2 < 32; m2++) acc[m2] = bias2[m2];
    }
    #pragma unroll 4
    for (int d = 0; d < 32; d++) {
        ull qd = pk(qrow[d]);
        const ull* krow = kh + d * 33;
        #pragma unroll
        for (int m2 = 0; m2 < 32; m2++) acc[m2] = fma2(qd, krow[m2], acc[m2]);
    }

    float p[64];
    #pragma unroll
    for (int m2 = 0; m2 < 32; m2++) {
        float2 f = upk(acc[m2]);
        p[2 * m2] = f.x; p[2 * m2 + 1] = f.y;
    }
    float mx = p[0];
    #pragma unroll
    for (int k = 1; k < 64; k++) mx = fmaxf(mx, p[k]);
    float sum = 0.f;
    #pragma unroll
    for (int k = 0; k < 64; k++) { p[k] = __expf(p[k] - mx); sum += p[k]; }
    float rinv = 1.f / sum;

    ull oacc[16];
    #pragma unroll
    for (int d2 = 0; d2 < 16; d2++) oacc[d2] = 0ull;
    #pragma unroll
    for (int m = 0; m < 64; m++) {
        ull pm = pk(p[m]);
        const float* vrow = vh + m * 34;
        #pragma unroll
        for (int d2 = 0; d2 < 16; d2++)
            oacc[d2] = fma2(pm, *(const ull*)(vrow + 2 * d2), oacc[d2]);
    }
    ull rr = pk(rinv);
    float* ob = g_attn + pixoff + (n >> 3) * 256 + (n & 7);
    #pragma unroll
    for (int d2 = 0; d2 < 16; d2++) {
        float2 f = upk(mul2(oacc[d2], rr));
        ob[(h * 32 + 2 * d2) * HW] = f.x;
        ob[(h * 32 + 2 * d2 + 1) * HW] = f.y;
    }
}

// ---------------------------------------------------------------------------
// K4: fused-z depthwise 5x5 + bias + attn -> D0 (g_Q), D1 (g_K). grid 6144.
// ---------------------------------------------------------------------------
__global__ __launch_bounds__(256)
void dw_kernel(const float* __restrict__ wdw, const float* __restrict__ bdw,
               const float* __restrict__ wdwa, const float* __restrict__ bdwa) {
    extern __shared__ float st[];
    float* s_h0 = st;                  // [20][264]
    float* s_h1 = st + 5280;
    float* s_w0 = st + 10560;
    float* s_w1 = st + 10592;

    int bx = blockIdx.x;               // 6144 = 16 * 96 * 4
    int yt = bx & 15;
    int v = bx >> 4;
    int c = v % 96, b = v / 96;
    int y0 = yt << 4;
    int tid = threadIdx.x;
    int chan = b * IMG + c * HW;
    const float* Vc  = g_V  + chan;
    const float* aVc = g_aV + chan;

    for (int l = tid; l < 5200; l += 256) {
        int r = l / 260, q = l - r * 260;
        int yy = y0 + r - 2; yy = yy < 0 ? -yy : (yy > 255 ? 510 - yy : yy);
        int xx = q - 2;      xx = xx < 0 ? -xx : (xx > 255 ? 510 - xx : xx);
        int ga = yy * 256 + xx;
        s_h0[r * 264 + q] = Vc[ga];
        s_h1[r * 264 + q] = aVc[ga];
    }
    if (tid < 25) { s_w0[tid] = wdw[c * 25 + tid]; s_w1[tid] = wdwa[c * 25 + tid]; }
    __syncthreads();

    int col = tid;
    float av[16];
    const float* ab = g_attn + chan + y0 * 256 + col;
    #pragma unroll
    for (int r = 0; r < 16; r++) av[r] = ab[r * 256];

    #pragma unroll
    for (int z = 0; z < 2; z++) {
        const float* sh = z ? s_h1 : s_h0;
        const float* sw = z ? s_w1 : s_w0;
        float bias = z ? __ldg(&bdwa[c]) : __ldg(&bdw[c]);
        float w[25];
        #pragma unroll
        for (int k = 0; k < 25; k++) w[k] = sw[k];

        float acc[16];
        #pragma unroll
        for (int r = 0; r < 16; r++) acc[r] = bias + av[r];

        #pragma unroll
        for (int rr = 0; rr < 20; rr++) {
            float xv[5];
            #pragma unroll
            for (int dx = 0; dx < 5; dx++) xv[dx] = sh[rr * 264 + col + dx];
            #pragma unroll
            for (int dy = 0; dy < 5; dy++) {
                int r = rr - dy;
                if (r >= 0 && r < 16) {
                    #pragma unroll
                    for (int dx = 0; dx < 5; dx++)
                        acc[r] = fmaf(xv[dx], w[dy * 5 + dx], acc[r]);
                }
            }
        }

        float* db = (z ? g_K : g_Q) + chan + y0 * 256 + col;
        #pragma unroll
        for (int r = 0; r < 16; r++)
            db[r * 256] = acc[r];
    }
}

// ---------------------------------------------------------------------------
extern "C" void kernel_launch(void* const* d_in, const int* in_sizes, int n_in,
                              void* d_out, int out_size) {
    const float* vision     = (const float*)d_in[0];
    const float* ass_vision = (const float*)d_in[1];
    const float* wv   = (const float*)d_in[2];
    const float* bv   = (const float*)d_in[3];
    const float* wav  = (const float*)d_in[4];
    const float* bav  = (const float*)d_in[5];
    const float* wqk  = (const float*)d_in[6];
    const float* bqk  = (const float*)d_in[7];
    // d_in[8..9]: waqk/baqk dead (reference bug: aaw unused, ass_attn_out = attn_out)
    const float* wdw  = (const float*)d_in[10];
    const float* bdw  = (const float*)d_in[11];
    const float* wdwa = (const float*)d_in[12];
    const float* bdwa = (const float*)d_in[13];
    const float* wp   = (const float*)d_in[14];
    const float* bp   = (const float*)d_in[15];
    const float* wpa  = (const float*)d_in[16];
    const float* bpa  = (const float*)d_in[17];
    const float* mw1  = (const float*)d_in[18];
    const float* mb1  = (const float*)d_in[19];
    const float* mw2  = (const float*)d_in[20];
    const float* mb2  = (const float*)d_in[21];
    float* out = (float*)d_out;

    float *pV, *paV, *pQ, *pK;
    cudaGetSymbolAddress((void**)&pV,  g_V);
    cudaGetSymbolAddress((void**)&paV, g_aV);
    cudaGetSymbolAddress((void**)&pQ,  g_Q);
    cudaGetSymbolAddress((void**)&pK,  g_K);

    const int SMEM_ATTN = 19200 * 4;   // 76800
    const int SMEM_DW   = 10624 * 4;   // 42496
    cudaFuncSetAttribute(conv_kernel, cudaFuncAttributeMaxDynamicSharedMemorySize, SM_TOTAL);
    cudaFuncSetAttribute(attn_kernel, cudaFuncAttributeMaxDynamicSharedMemorySize, SMEM_ATTN);
    cudaFuncSetAttribute(dw_kernel,   cudaFuncAttributeMaxDynamicSharedMemorySize, SMEM_DW);

    bias_kernel<<<16, 256>>>(mw1, mb1, mw2, mb2);

    // V, Q (pre-scaled), K, aV: 4 independent jobs
    ConvJob jV  = { vision,     wv,         bv,       pV,  1.0f };
    ConvJob jQ  = { vision,     wqk,        bqk,      pQ,  SCALE };
    ConvJob jK  = { vision,     wqk + 9216, bqk + 96, pK,  1.0f };
    ConvJob jaV = { ass_vision, wav,        bav,      paV, 1.0f };
    conv_kernel<<<dim3(2048, 1, 4), 256, SM_TOTAL>>>(jV, jQ, jK, jaV);

    // window attention: 4096 windows, 192 threads (3 heads x 64 rows)
    attn_kernel<<<4096, 192, SMEM_ATTN>>>();

    // depthwise + attn add -> D0 (g_Q), D1 (g_K)
    dw_kernel<<<6144, 256, SMEM_DW>>>(wdw, bdw, wdwa, bdwa);

    // final projections
    ConvJob jP0 = { pQ, wp,  bp,  out,        1.0f };
    ConvJob jP1 = { pK, wpa, bpa, out + NPIX, 1.0f };
    conv_kernel<<<dim3(2048, 1, 2), 256, SM_TOTAL>>>(jP0, jP1, jP0, jP0);
}

// round 10
// speedup vs baseline: 1.2114x; 1.0221x over previous
#include <cuda_runtime.h>
#include <math.h>

#define HW   65536
#define IMG  6291456          // 96*65536
#define NPIX 25165824         // 4*96*65536
#define SCALE 0.17677669529663687f

typedef unsigned long long ull;

// Full-batch buffers. g_Q / g_K are reused as D0 / D1 scratch after attention.
static __device__ __align__(16) float g_V[NPIX];
static __device__ __align__(16) float g_aV[NPIX];
static __device__ __align__(16) float g_Q[NPIX];
static __device__ __align__(16) float g_K[NPIX];
static __device__ __align__(16) float g_attn[NPIX];
static __device__ __align__(16) float g_bias[3 * 64 * 64];

// ---- f32x2 packed helpers (attention) --------------------------------------
__device__ __forceinline__ ull pk(float x) {
    ull r; asm("mov.b64 %0, {%1, %1};" : "=l"(r) : "f"(x)); return r;
}
__device__ __forceinline__ float2 upk(ull v) {
    float2 f; asm("mov.b64 {%0, %1}, %2;" : "=f"(f.x), "=f"(f.y) : "l"(v)); return f;
}
__device__ __forceinline__ ull fma2(ull a, ull b, ull c) {
    ull r; asm("fma.rn.f32x2 %0, %1, %2, %3;" : "=l"(r) : "l"(a), "l"(b), "l"(c)); return r;
}
__device__ __forceinline__ ull mul2(ull a, ull b) {
    ull r; asm("mul.rn.f32x2 %0, %1, %2;" : "=l"(r) : "l"(a), "l"(b)); return r;
}

// ---- mma.sync helpers -------------------------------------------------------
__device__ __forceinline__ unsigned smem_u32(const void* p) {
    unsigned a;
    asm("{ .reg .u64 t; cvta.to.shared.u64 t, %1; cvt.u32.u64 %0, t; }" : "=r"(a) : "l"(p));
    return a;
}
__device__ __forceinline__ void ldsm4(unsigned* r, unsigned addr) {
    asm volatile("ldmatrix.sync.aligned.m8n8.x4.shared.b16 {%0,%1,%2,%3}, [%4];"
                 : "=r"(r[0]), "=r"(r[1]), "=r"(r[2]), "=r"(r[3]) : "r"(addr));
}
__device__ __forceinline__ void mma_bf16(float* c, const unsigned* a, unsigned b0, unsigned b1) {
    asm volatile(
        "mma.sync.aligned.m16n8k16.row.col.f32.bf16.bf16.f32 "
        "{%0,%1,%2,%3}, {%4,%5,%6,%7}, {%8,%9}, {%0,%1,%2,%3};"
        : "+f"(c[0]), "+f"(c[1]), "+f"(c[2]), "+f"(c[3])
        : "r"(a[0]), "r"(a[1]), "r"(a[2]), "r"(a[3]), "r"(b0), "r"(b1));
}
// pack 2 floats -> bf16x2 {lo=v0, hi=v1}
__device__ __forceinline__ unsigned cvt2(float v0, float v1) {
    unsigned r; asm("cvt.rn.bf16x2.f32 %0, %1, %2;" : "=r"(r) : "f"(v1), "f"(v0)); return r;
}

// swizzled smem byte offsets: row stride 384 B, 16B-window XOR by (row&7)
__device__ __forceinline__ int physA(int px, int kb) { return px * 384 + (kb ^ ((px & 7) << 4)); }
__device__ __forceinline__ int physB(int o,  int kb) { return o  * 384 + (kb ^ ((o  & 7) << 4)); }

#define SM_A 0
#define SM_B 49152
#define SM_BIAS 86016
#define SM_TOTAL 87424

// ---------------------------------------------------------------------------
// K1: relative-position bias MLP
// ---------------------------------------------------------------------------
__device__ __forceinline__ float sgnlog(int d) {
    float l = log1pf(fabsf((float)d));
    return d < 0 ? -l : l;
}

__global__ void bias_kernel(const float* __restrict__ mw1, const float* __restrict__ mb1,
                            const float* __restrict__ mw2, const float* __restrict__ mb2) {
    int t = blockIdx.x * 256 + threadIdx.x;
    if (t >= 4096) return;
    int i = t >> 6, j = t & 63;
    float r0 = sgnlog((i >> 3) - (j >> 3));
    float r1 = sgnlog((i & 7) - (j & 7));
    float a0 = 0.f, a1 = 0.f, a2 = 0.f;
    for (int h = 0; h < 256; h++) {
        float hid = fmaf(r0, mw1[h], fmaf(r1, mw1[256 + h], mb1[h]));
        hid = fmaxf(hid, 0.f);
        a0 = fmaf(hid, mw2[h * 3 + 0], a0);
        a1 = fmaf(hid, mw2[h * 3 + 1], a1);
        a2 = fmaf(hid, mw2[h * 3 + 2], a2);
    }
    g_bias[t]        = a0 + mb2[0];
    g_bias[4096 + t] = a1 + mb2[1];
    g_bias[8192 + t] = a2 + mb2[2];
}

// ---------------------------------------------------------------------------
// Shared conv building blocks (mma.sync bf16 split-2)
// ---------------------------------------------------------------------------
__device__ __forceinline__ void conv_a_convert(char* raw, const float* inb, int wid, int lane) {
    int c2 = lane >> 3, pxl = lane & 7;   // 4 c-pairs x 8 px per warp-iter
    #pragma unroll 4
    for (int it = 0; it < 24; it++) {
        int g = it * 8 + wid;             // 0..191
        int po = g & 15, cq = g >> 4;     // 16 px-octets x 12 c-quads
        int c = cq * 8 + c2 * 2;
        int px = po * 8 + pxl;
        float v0 = inb[c * HW + px];
        float v1 = inb[(c + 1) * HW + px];
        unsigned hi = cvt2(v0, v1);
        float h0 = __uint_as_float(hi << 16);
        float h1 = __uint_as_float(hi & 0xffff0000u);
        unsigned lo = cvt2(v0 - h0, v1 - h1);
        *(unsigned*)(raw + SM_A + physA(px, c * 2))       = hi;
        *(unsigned*)(raw + SM_A + physA(px, 192 + c * 2)) = lo;
    }
}

__device__ __forceinline__ void conv_b_convert(char* raw, const float* w, int tid) {
    for (int l = tid; l < 4608; l += 256) {
        int o = l / 48, cp = l - (l / 48) * 48;
        int c = cp * 2;
        float2 wv = upk(*(const ull*)(w + o * 96 + c));
        unsigned hi = cvt2(wv.x, wv.y);
        float h0 = __uint_as_float(hi << 16);
        float h1 = __uint_as_float(hi & 0xffff0000u);
        unsigned lo = cvt2(wv.x - h0, wv.y - h1);
        *(unsigned*)(raw + SM_B + physB(o, c * 2))       = hi;
        *(unsigned*)(raw + SM_B + physB(o, 192 + c * 2)) = lo;
    }
}

// mainloop + epilogue. Caller must __syncthreads() before (B ready).
// Performs its own __syncthreads() after ldsm (so caller may overwrite B next),
// then the epilogue STGs (overlap the caller's next-phase B conversion).
__device__ __forceinline__ void conv_mma_epi(
    char* raw, const float* s_bias_p, float* outb, float scl,
    int wid, int lane)
{
    unsigned sA32 = smem_u32(raw + SM_A);
    unsigned sB32 = smem_u32(raw + SM_B);
    int wm = wid >> 1, wn = wid & 1;
    int gr = lane & 7, gi = lane >> 3;
    int swz = gr << 4;
    int kextA = (gi >> 1) << 4;   // bytes
    int kextB = (gi & 1) << 4;
    int aRow[2], bRow[3];
    #pragma unroll
    for (int tm = 0; tm < 2; tm++)
        aRow[tm] = (wm * 32 + tm * 16 + gr + (gi & 1) * 8) * 384;
    #pragma unroll
    for (int tp = 0; tp < 3; tp++)
        bRow[tp] = (wn * 48 + tp * 16 + gr + (gi >> 1) * 8) * 384;

    float c[2][6][4];
    #pragma unroll
    for (int tm = 0; tm < 2; tm++)
        #pragma unroll
        for (int tn = 0; tn < 6; tn++)
            #pragma unroll
            for (int q = 0; q < 4; q++) c[tm][tn][q] = 0.f;

    #pragma unroll
    for (int t = 0; t < 3; t++) {
        int kaB = (t == 2) ? 192 : 0;     // A lo for term 2
        int kbB = (t == 1) ? 192 : 0;     // B lo for term 1
        #pragma unroll
        for (int ks = 0; ks < 6; ks++) {
            unsigned aF[2][4], bF[3][4];
            int ka = kaB + ks * 32;
            int kb = kbB + ks * 32;
            #pragma unroll
            for (int tm = 0; tm < 2; tm++)
                ldsm4(aF[tm], sA32 + aRow[tm] + ((ka + kextA) ^ swz));
            #pragma unroll
            for (int tp = 0; tp < 3; tp++)
                ldsm4(bF[tp], sB32 + bRow[tp] + ((kb + kextB) ^ swz));
            #pragma unroll
            for (int tm = 0; tm < 2; tm++)
                #pragma unroll
                for (int tn = 0; tn < 6; tn++) {
                    int tp = tn >> 1, r0 = (tn & 1) * 2;
                    mma_bf16(c[tm][tn], aF[tm], bF[tp][r0], bF[tp][r0 + 1]);
                }
        }
    }
    __syncthreads();   // all ldsm done -> B buffer reusable by caller

    int pr = lane >> 2, oc = (lane & 3) * 2;
    #pragma unroll
    for (int tm = 0; tm < 2; tm++) {
        int pxr = wm * 32 + tm * 16 + pr;
        #pragma unroll
        for (int tn = 0; tn < 6; tn++) {
            int o0 = wn * 48 + tn * 8 + oc;
            float b0 = s_bias_p[o0], b1 = s_bias_p[o0 + 1];
            outb[o0 * HW + pxr]            = (c[tm][tn][0] + b0) * scl;
            outb[(o0 + 1) * HW + pxr]      = (c[tm][tn][1] + b1) * scl;
            outb[o0 * HW + pxr + 8]        = (c[tm][tn][2] + b0) * scl;
            outb[(o0 + 1) * HW + pxr + 8]  = (c[tm][tn][3] + b1) * scl;
        }
    }
}

// ---------------------------------------------------------------------------
// K2a: phased V/Q/K conv1x1 — one A conversion, three B phases. grid 2048.
// ---------------------------------------------------------------------------
__global__ __launch_bounds__(256, 2)
void conv3_kernel(const float* __restrict__ vision,
                  const float* __restrict__ wv,  const float* __restrict__ bv,
                  const float* __restrict__ wqk, const float* __restrict__ bqk) {
    extern __shared__ __align__(16) char raw[];
    float* s_bias = (float*)(raw + SM_BIAS);

    int tid = threadIdx.x;
    int wid = tid >> 5, lane = tid & 31;
    int bx = blockIdx.x;
    int b = bx >> 9, px0 = (bx & 511) << 7;
    const float* inb = vision + b * IMG + px0;
    int gbase = b * IMG + px0;

    // all three bias vectors up front
    if (tid < 96)        s_bias[tid]        = bv[tid];
    else if (tid < 192)  s_bias[tid]        = bqk[tid - 96];        // Q bias at +96
    if (tid < 96)        s_bias[192 + tid]  = bqk[96 + tid];        // K bias at +192

    conv_a_convert(raw, inb, wid, lane);

    // phase 0: V
    conv_b_convert(raw, wv, tid);
    __syncthreads();
    conv_mma_epi(raw, s_bias, g_V + gbase, 1.0f, wid, lane);

    // phase 1: Q (pre-scaled)
    conv_b_convert(raw, wqk, tid);
    __syncthreads();
    conv_mma_epi(raw, s_bias + 96, g_Q + gbase, SCALE, wid, lane);

    // phase 2: K
    conv_b_convert(raw, wqk + 9216, tid);
    __syncthreads();
    conv_mma_epi(raw, s_bias + 192, g_K + gbase, 1.0f, wid, lane);
}

// ---------------------------------------------------------------------------
// K2b: generic 1-2 job conv1x1 (z selects). Used for aV and final projections.
// ---------------------------------------------------------------------------
struct ConvJob { const float* in; const float* w; const float* bias; float* out; float scale; };

__global__ __launch_bounds__(256, 2)
void conv_kernel(ConvJob j0, ConvJob j1) {
    ConvJob j = blockIdx.z ? j1 : j0;
    extern __shared__ __align__(16) char raw[];
    float* s_bias = (float*)(raw + SM_BIAS);

    int tid = threadIdx.x;
    int wid = tid >> 5, lane = tid & 31;
    int bx = blockIdx.x;
    int b = bx >> 9, px0 = (bx & 511) << 7;
    const float* inb = j.in + b * IMG + px0;

    if (tid < 96) s_bias[tid] = j.bias[tid];
    conv_a_convert(raw, inb, wid, lane);
    conv_b_convert(raw, j.w, tid);
    __syncthreads();
    conv_mma_epi(raw, s_bias, j.out + b * IMG + px0, j.scale, wid, lane);
}

// ---------------------------------------------------------------------------
// K3: window attention — one thread per (head, row); one barrier.
// smem floats: s_q[3][64*33] | s_k ull[3][32*33] | s_v[3][64*34] = 76800 B
// ---------------------------------------------------------------------------
__global__ __launch_bounds__(192, 2)
void attn_kernel() {
    extern __shared__ float sm[];
    float* s_q = sm;                      // [h][n*33+d]
    ull*   s_k = (ull*)(sm + 6336);       // [h][d*33+m2]
    float* s_v = sm + 12672;              // [h][m*34+d]

    int tid = threadIdx.x;
    int blk = blockIdx.x;
    int b = blk >> 10, wy = (blk >> 5) & 31, wx = blk & 31;
    int pixoff = b * IMG + wy * 2048 + wx * 8;

    for (int l = tid; l < 3072; l += 192) {
        int hh = l >> 10;
        int r = l & 1023;
        int d = r >> 5, n2 = r & 31;
        int ga = pixoff + (hh * 32 + d) * HW + (n2 >> 2) * 256 + (n2 & 3) * 2;
        float2 q = upk(*(const ull*)(g_Q + ga));
        s_q[hh * 2112 + (2 * n2) * 33 + d] = q.x;
        s_q[hh * 2112 + (2 * n2 + 1) * 33 + d] = q.y;
        s_k[hh * 1056 + d * 33 + n2] = *(const ull*)(g_K + ga);
        float2 v = upk(*(const ull*)(g_V + ga));
        s_v[hh * 2176 + (2 * n2) * 34 + d] = v.x;
        s_v[hh * 2176 + (2 * n2 + 1) * 34 + d] = v.y;
    }
    __syncthreads();

    int h = tid >> 6, n = tid & 63;
    const float* qrow = s_q + h * 2112 + n * 33;
    const ull*   kh   = s_k + h * 1056;
    const float* vh   = s_v + h * 2176;

    ull acc[32];
    {
        const ull* bias2 = (const ull*)(g_bias + h * 4096 + n * 64);
        #pragma unroll
        for (int m2 = 0; m2 < 32; m2++) acc[m2] = bias2[m2];
    }
    #pragma unroll 4
    for (int d = 0; d < 32; d++) {
        ull qd = pk(qrow[d]);
        const ull* krow = kh + d * 33;
        #pragma unroll
        for (int m2 = 0; m2 < 32; m2++) acc[m2] = fma2(qd, krow[m2], acc[m2]);
    }

    float p[64];
    #pragma unroll
    for (int m2 = 0; m2 < 32; m2++) {
        float2 f = upk(acc[m2]);
        p[2 * m2] = f.x; p[2 * m2 + 1] = f.y;
    }
    float mx = p[0];
    #pragma unroll
    for (int k = 1; k < 64; k++) mx = fmaxf(mx, p[k]);
    float sum = 0.f;
    #pragma unroll
    for (int k = 0; k < 64; k++) { p[k] = __expf(p[k] - mx); sum += p[k]; }
    float rinv = 1.f / sum;

    ull oacc[16];
    #pragma unroll
    for (int d2 = 0; d2 < 16; d2++) oacc[d2] = 0ull;
    #pragma unroll
    for (int m = 0; m < 64; m++) {
        ull pm = pk(p[m]);
        const float* vrow = vh + m * 34;
        #pragma unroll
        for (int d2 = 0; d2 < 16; d2++)
            oacc[d2] = fma2(pm, *(const ull*)(vrow + 2 * d2), oacc[d2]);
    }
    ull rr = pk(rinv);
    float* ob = g_attn + pixoff + (n >> 3) * 256 + (n & 7);
    #pragma unroll
    for (int d2 = 0; d2 < 16; d2++) {
        float2 f = upk(mul2(oacc[d2], rr));
        ob[(h * 32 + 2 * d2) * HW] = f.x;
        ob[(h * 32 + 2 * d2 + 1) * HW] = f.y;
    }
}

// ---------------------------------------------------------------------------
// K4: fused-z depthwise 5x5 + bias + attn -> D0 (g_Q), D1 (g_K). grid 6144.
// ---------------------------------------------------------------------------
__global__ __launch_bounds__(256)
void dw_kernel(const float* __restrict__ wdw, const float* __restrict__ bdw,
               const float* __restrict__ wdwa, const float* __restrict__ bdwa) {
    extern __shared__ float st[];
    float* s_h0 = st;                  // [20][264]
    float* s_h1 = st + 5280;
    float* s_w0 = st + 10560;
    float* s_w1 = st + 10592;

    int bx = blockIdx.x;               // 6144 = 16 * 96 * 4
    int yt = bx & 15;
    int v = bx >> 4;
    int c = v % 96, b = v / 96;
    int y0 = yt << 4;
    int tid = threadIdx.x;
    int chan = b * IMG + c * HW;
    const float* Vc  = g_V  + chan;
    const float* aVc = g_aV + chan;

    for (int l = tid; l < 5200; l += 256) {
        int r = l / 260, q = l - r * 260;
        int yy = y0 + r - 2; yy = yy < 0 ? -yy : (yy > 255 ? 510 - yy : yy);
        int xx = q - 2;      xx = xx < 0 ? -xx : (xx > 255 ? 510 - xx : xx);
        int ga = yy * 256 + xx;
        s_h0[r * 264 + q] = Vc[ga];
        s_h1[r * 264 + q] = aVc[ga];
    }
    if (tid < 25) { s_w0[tid] = wdw[c * 25 + tid]; s_w1[tid] = wdwa[c * 25 + tid]; }
    __syncthreads();

    int col = tid;
    float av[16];
    const float* ab = g_attn + chan + y0 * 256 + col;
    #pragma unroll
    for (int r = 0; r < 16; r++) av[r] = ab[r * 256];

    #pragma unroll
    for (int z = 0; z < 2; z++) {
        const float* sh = z ? s_h1 : s_h0;
        const float* sw = z ? s_w1 : s_w0;
        float bias = z ? __ldg(&bdwa[c]) : __ldg(&bdw[c]);
        float w[25];
        #pragma unroll
        for (int k = 0; k < 25; k++) w[k] = sw[k];

        float acc[16];
        #pragma unroll
        for (int r = 0; r < 16; r++) acc[r] = bias + av[r];

        #pragma unroll
        for (int rr = 0; rr < 20; rr++) {
            float xv[5];
            #pragma unroll
            for (int dx = 0; dx < 5; dx++) xv[dx] = sh[rr * 264 + col + dx];
            #pragma unroll
            for (int dy = 0; dy < 5; dy++) {
                int r = rr - dy;
                if (r >= 0 && r < 16) {
                    #pragma unroll
                    for (int dx = 0; dx < 5; dx++)
                        acc[r] = fmaf(xv[dx], w[dy * 5 + dx], acc[r]);
                }
            }
        }

        float* db = (z ? g_K : g_Q) + chan + y0 * 256 + col;
        #pragma unroll
        for (int r = 0; r < 16; r++)
            db[r * 256] = acc[r];
    }
}

// ---------------------------------------------------------------------------
extern "C" void kernel_launch(void* const* d_in, const int* in_sizes, int n_in,
                              void* d_out, int out_size) {
    const float* vision     = (const float*)d_in[0];
    const float* ass_vision = (const float*)d_in[1];
    const float* wv   = (const float*)d_in[2];
    const float* bv   = (const float*)d_in[3];
    const float* wav  = (const float*)d_in[4];
    const float* bav  = (const float*)d_in[5];
    const float* wqk  = (const float*)d_in[6];
    const float* bqk  = (const float*)d_in[7];
    // d_in[8..9]: waqk/baqk dead (reference bug: aaw unused, ass_attn_out = attn_out)
    const float* wdw  = (const float*)d_in[10];
    const float* bdw  = (const float*)d_in[11];
    const float* wdwa = (const float*)d_in[12];
    const float* bdwa = (const float*)d_in[13];
    const float* wp   = (const float*)d_in[14];
    const float* bp   = (const float*)d_in[15];
    const float* wpa  = (const float*)d_in[16];
    const float* bpa  = (const float*)d_in[17];
    const float* mw1  = (const float*)d_in[18];
    const float* mb1  = (const float*)d_in[19];
    const float* mw2  = (const float*)d_in[20];
    const float* mb2  = (const float*)d_in[21];
    float* out = (float*)d_out;

    float *paV, *pQ, *pK;
    cudaGetSymbolAddress((void**)&paV, g_aV);
    cudaGetSymbolAddress((void**)&pQ,  g_Q);
    cudaGetSymbolAddress((void**)&pK,  g_K);

    const int SMEM_ATTN = 19200 * 4;   // 76800
    const int SMEM_DW   = 10624 * 4;   // 42496
    cudaFuncSetAttribute(conv3_kernel, cudaFuncAttributeMaxDynamicSharedMemorySize, SM_TOTAL);
    cudaFuncSetAttribute(conv_kernel,  cudaFuncAttributeMaxDynamicSharedMemorySize, SM_TOTAL);
    cudaFuncSetAttribute(attn_kernel,  cudaFuncAttributeMaxDynamicSharedMemorySize, SMEM_ATTN);
    cudaFuncSetAttribute(dw_kernel,    cudaFuncAttributeMaxDynamicSharedMemorySize, SMEM_DW);

    bias_kernel<<<16, 256>>>(mw1, mb1, mw2, mb2);

    // V, Q (pre-scaled), K from ONE vision tile read/conversion per block
    conv3_kernel<<<2048, 256, SM_TOTAL>>>(vision, wv, bv, wqk, bqk);

    // window attention (needs only V/Q/K) — start before aV
    attn_kernel<<<4096, 192, SMEM_ATTN>>>();

    // aV projection (needed only by dw)
    ConvJob jaV = { ass_vision, wav, bav, paV, 1.0f };
    conv_kernel<<<dim3(2048, 1, 1), 256, SM_TOTAL>>>(jaV, jaV);

    // depthwise + attn add -> D0 (g_Q), D1 (g_K)
    dw_kernel<<<6144, 256, SMEM_DW>>>(wdw, bdw, wdwa, bdwa);

    // final projections
    ConvJob jP0 = { pQ, wp,  bp,  out,        1.0f };
    ConvJob jP1 = { pK, wpa, bpa, out + NPIX, 1.0f };
    conv_kernel<<<dim3(2048, 1, 2), 256, SM_TOTAL>>>(jP0, jP1);
}